// round 13
// baseline (speedup 1.0000x reference)
#include <cuda_runtime.h>
#include <mma.h>
#include <cstdint>
using namespace nvcuda;

#define S_ 4
#define N_ 32768
#define K_ 256
#define H_ 100
#define NB 256
#define NBW 2048
#define NT 256
#define SA 108
#define SW2 116
#define SB3 72
#define CHT (104*SB3)

#define OFF_HS 0
#define OFF_BA 55296
#define BUFB   (2*CHT*4)
#define OFF_SC (OFF_BA+119808)
#define OFF_US (OFF_SC+16384)
#define OFF_B2 (OFF_US+1024)
#define OFF_B3 (OFF_B2+448)
#define SMEM_TOTAL (OFF_B3+2048)

__device__ float g_w2h[H_*H_], g_w2l[H_*H_];
__device__ float g_w3h[H_*2*K_], g_w3l[H_*2*K_];
__device__ float g_part[(size_t)S_*5*NBW*K_];
__device__ float g_w[S_*K_*2];

static __device__ __forceinline__ float tf32f(float x){
    uint32_t r; asm("cvt.rna.tf32.f32 %0, %1;" : "=r"(r) : "f"(x));
    return __uint_as_float(r);
}
static __device__ __forceinline__ unsigned smem_u32(const void* p){
    return (unsigned)__cvta_generic_to_shared(p);
}
static __device__ __forceinline__ void cpa16(unsigned dst, const float* src){
    asm volatile("cp.async.cg.shared.global [%0], [%1], 16;\n" :: "r"(dst), "l"(src));
}
#define CPA_COMMIT() asm volatile("cp.async.commit_group;\n" ::: "memory")
#define CPA_WAIT1()  asm volatile("cp.async.wait_group 1;\n" ::: "memory")
#define CPA_WAIT0()  asm volatile("cp.async.wait_group 0;\n" ::: "memory")

typedef wmma::fragment<wmma::matrix_a,16,16,8,wmma::precision::tf32,wmma::row_major> FragA;
typedef wmma::fragment<wmma::matrix_b,16,16,8,wmma::precision::tf32,wmma::row_major> FragB;
typedef wmma::fragment<wmma::accumulator,16,16,8,float> FragC;

__global__ void round_kernel(const float* __restrict__ W2, const float* __restrict__ W3){
    int i = blockIdx.x*256 + threadIdx.x;
    if(i < H_*H_){
        float v=W2[i], h=tf32f(v);
        g_w2h[i]=h; g_w2l[i]=tf32f(v-h);
    }
    if(i < H_*2*K_){
        float v=W3[i], h=tf32f(v);
        g_w3h[i]=h; g_w3l[i]=tf32f(v-h);
    }
}

// stage chunk c (32 LP cols + 32 MU cols, hi & lo) into buffer B
static __device__ __forceinline__ void stage3(char* B, int c, int tid){
    for(int idx=tid; idx<3200; idx+=NT){
        int part = (idx>=1600), j = part? idx-1600 : idx;
        int r=j>>4, t=j&15, mu=t>>3, sg=t&7;
        const float* src = (part? g_w3l : g_w3h) + (size_t)r*512 + mu*256 + c*32 + sg*4;
        cpa16(smem_u32((float*)B + part*CHT + r*SB3 + mu*32 + sg*4), src);
    }
}

static __device__ void gemm3_chunk(int c, const float* Bh, const float* hS,
    const float* uS, const float* b3S, float* sc, int s, int blk, int w, int lid)
{
    const float* Bl = Bh + CHT;
    FragA fa; FragB fb;
    FragC fL[2], fM[2];
    #pragma unroll
    for(int t=0;t<2;++t){ wmma::fill_fragment(fL[t],0.f); wmma::fill_fragment(fM[t],0.f); }
    for(int k=0;k<13;++k){
        wmma::load_matrix_sync(fa, hS + (w*16)*SA + k*8, SA);
        #pragma unroll
        for(int t=0;t<2;++t){
            wmma::load_matrix_sync(fb, Bh + k*8*SB3 + t*16, SB3);      wmma::mma_sync(fL[t],fa,fb,fL[t]);
            wmma::load_matrix_sync(fb, Bl + k*8*SB3 + t*16, SB3);      wmma::mma_sync(fL[t],fa,fb,fL[t]);
            wmma::load_matrix_sync(fb, Bh + k*8*SB3 + 32 + t*16, SB3); wmma::mma_sync(fM[t],fa,fb,fM[t]);
            wmma::load_matrix_sync(fb, Bl + k*8*SB3 + 32 + t*16, SB3); wmma::mma_sync(fM[t],fa,fb,fM[t]);
        }
    }
    #pragma unroll
    for(int t=0;t<2;++t){
        wmma::store_matrix_sync(sc,     fL[t], 16, wmma::mem_row_major);
        wmma::store_matrix_sync(sc+256, fM[t], 16, wmma::mem_row_major);
        __syncwarp();
        int col=lid&15, rh=lid>>4;
        int kg=c*32+t*16+col;
        float bl=b3S[kg], bm=b3S[256+kg];
        float a=0,b=0,cc=0,d=0,e=0;
        #pragma unroll
        for(int r8=0;r8<8;++r8){
            int r=rh*8+r8, gr=w*16+r;
            float u0=uS[gr], u1=uS[128+gr];
            float p =__expf(sc[r*16+col]+bl);
            float pm=p*(sc[256+r*16+col]+bm);
            a+=p*u0*u0; b+=p*u0*u1; cc+=p*u1*u1; d+=pm*u0; e+=pm*u1;
        }
        a+=__shfl_xor_sync(0xffffffffu,a,16);
        b+=__shfl_xor_sync(0xffffffffu,b,16);
        cc+=__shfl_xor_sync(0xffffffffu,cc,16);
        d+=__shfl_xor_sync(0xffffffffu,d,16);
        e+=__shfl_xor_sync(0xffffffffu,e,16);
        if(lid<16){
            size_t base=(((size_t)s*5)*NBW+(size_t)(blk*8+w))*K_ + kg;
            const size_t cs=(size_t)NBW*K_;
            g_part[base]=a; g_part[base+cs]=b; g_part[base+2*cs]=cc;
            g_part[base+3*cs]=d; g_part[base+4*cs]=e;
        }
        __syncwarp();
    }
}

__global__ void __launch_bounds__(NT,1)
stageA_kernel(const float* __restrict__ U,  const float* __restrict__ W1,
              const float* __restrict__ b1, const float* __restrict__ b2,
              const float* __restrict__ b3)
{
    extern __shared__ char smc[];
    float* hS =(float*)(smc+OFF_HS);
    char*  BA = smc+OFF_BA;
    float* SC =(float*)(smc+OFF_SC);
    float* uS =(float*)(smc+OFF_US);
    float* b2S=(float*)(smc+OFF_B2);
    float* b3S=(float*)(smc+OFF_B3);
    const int tid=threadIdx.x, w=tid>>5, lid=tid&31;
    const int s=blockIdx.y, blk=blockIdx.x;
    float* sc = SC + w*512;

    for(int i=tid;i<7488;i+=NT) ((float4*)BA)[i]=make_float4(0.f,0.f,0.f,0.f);
    if(tid<128){
        const float* up=U+((size_t)(s*N_+blk*128+tid)<<1);
        uS[tid]=up[0]; uS[128+tid]=up[1];
    }
    if(tid<112) b2S[tid]=(tid<H_)?b2[tid]:0.f;
    for(int i=tid;i<512;i+=NT) b3S[i]=b3[i];
    __syncthreads();

    // stage W2h/W2l (rows 0..99, cols 0..99)  [group 1]
    for(int idx=tid; idx<5000; idx+=NT){
        int part=(idx>=2500), j=part?idx-2500:idx;
        int r=j/25, sg=j-r*25;
        const float* src=(part? g_w2l:g_w2h)+r*H_+sg*4;
        cpa16(smem_u32((float*)BA + part*12064 + r*SW2 + sg*4), src);
    }
    CPA_COMMIT();

    // h1 = relu(U@W1+b1), tf32-rounded; cols 100..103 zero
    for(int idx=tid;idx<128*104;idx+=NT){
        int m=idx/104, i=idx-m*104;
        float v=(i<H_)?fmaxf(fmaf(uS[m],W1[i],fmaf(uS[128+m],W1[H_+i],b1[i])),0.f):0.f;
        hS[m*SA+i]=tf32f(v);
    }
    CPA_WAIT0(); __syncthreads();

    // GEMM2: 7 n-tiles, hi+lo, k=13x8
    {
        const float* W2hS=(float*)BA;
        const float* W2lS=(float*)BA+12064;
        FragA fa; FragB fb; FragC fc[7];
        #pragma unroll
        for(int t=0;t<7;++t) wmma::fill_fragment(fc[t],0.f);
        for(int k=0;k<13;++k){
            wmma::load_matrix_sync(fa, hS+(w*16)*SA+k*8, SA);
            #pragma unroll
            for(int t=0;t<7;++t){
                wmma::load_matrix_sync(fb, W2hS+k*8*SW2+t*16, SW2); wmma::mma_sync(fc[t],fa,fb,fc[t]);
                wmma::load_matrix_sync(fb, W2lS+k*8*SW2+t*16, SW2); wmma::mma_sync(fc[t],fa,fb,fc[t]);
            }
        }
        // h2 writeback (warp-private rows)
        #pragma unroll
        for(int t=0;t<7;++t){
            wmma::store_matrix_sync(sc, fc[t], 16, wmma::mem_row_major);
            __syncwarp();
            for(int e2=lid;e2<256;e2+=32){
                int r=e2>>4, c2=e2&15, j=t*16+c2;
                if(j<104) hS[(w*16+r)*SA+j]=tf32f(fmaxf(sc[e2]+b2S[j],0.f));
            }
            __syncwarp();
        }
    }
    __syncthreads();

    // zero pad rows 100..103 (hi & lo tiles, both buffers), then stage chunks 0,1
    for(int i=tid;i<2*2*4*SB3;i+=NT){
        int bu=i/(2*4*SB3);
        int rem=i-bu*(2*4*SB3);
        int part=rem/(4*SB3);
        int rr=rem-part*(4*SB3);
        ((float*)(BA+(size_t)bu*BUFB))[part*CHT + 100*SB3 + rr]=0.f;
    }
    stage3(BA, 0, tid);       CPA_COMMIT();
    stage3(BA+BUFB, 1, tid);  CPA_COMMIT();
    CPA_WAIT1(); __syncthreads();

    for(int c=0;c<8;++c){
        gemm3_chunk(c, (float*)(BA+(size_t)(c&1)*BUFB), hS, uS, b3S, sc, s, blk, w, lid);
        if(c==7) break;
        __syncthreads();
        if(c<6){ stage3(BA+(size_t)(c&1)*BUFB, c+2, tid); CPA_COMMIT(); CPA_WAIT1(); }
        else   { CPA_WAIT0(); }
        __syncthreads();
    }
}

__global__ void __launch_bounds__(1024) stageB_kernel(const float* __restrict__ eps,
                                                      float* __restrict__ kl_out)
{
    __shared__ float sm5[5][4][K_];
    __shared__ float red[K_];
    const int s=blockIdx.x, tid=threadIdx.x, k=tid&255, q=tid>>8;
    const float* base=g_part+((size_t)s*5*NBW)*K_+k;
    const size_t cs=(size_t)NBW*K_;
    float A=0,B=0,C=0,dd=0,ee=0;
    for(int b=q*512;b<q*512+512;++b){
        size_t o=(size_t)b*K_;
        A+=base[o]; B+=base[cs+o]; C+=base[2*cs+o]; dd+=base[3*cs+o]; ee+=base[4*cs+o];
    }
    sm5[0][q][k]=A; sm5[1][q][k]=B; sm5[2][q][k]=C; sm5[3][q][k]=dd; sm5[4][q][k]=ee;
    __syncthreads();
    if(q==0){
        A =sm5[0][0][k]+sm5[0][1][k]+sm5[0][2][k]+sm5[0][3][k]+1.f;
        B =sm5[1][0][k]+sm5[1][1][k]+sm5[1][2][k]+sm5[1][3][k];
        C =sm5[2][0][k]+sm5[2][1][k]+sm5[2][2][k]+sm5[2][3][k]+1.f;
        dd=sm5[3][0][k]+sm5[3][1][k]+sm5[3][2][k]+sm5[3][3][k];
        ee=sm5[4][0][k]+sm5[4][1][k]+sm5[4][2][k]+sm5[4][3][k];
        float det=A*C-B*B, inv=1.f/det;
        float c00=C*inv, c01=-B*inv, c11=A*inv;
        float qm0=c00*dd+c01*ee, qm1=c01*dd+c11*ee;
        float l00=sqrtf(c00), l10=c01/l00, l11=sqrtf(fmaxf(c11-l10*l10,0.f));
        float e0=eps[(s*K_+k)*2], e1=eps[(s*K_+k)*2+1];
        g_w[(s*K_+k)*2]  =qm0+l00*e0;
        g_w[(s*K_+k)*2+1]=qm1+l10*e0+l11*e1;
        red[k]=0.5f*((c00+c11)+(qm0*qm0+qm1*qm1)-2.f+logf(det));
    }
    __syncthreads();
    for(int off=128;off;off>>=1){
        if(tid<off) red[tid]+=red[tid+off];
        __syncthreads();
    }
    if(tid==0) kl_out[s]=red[0];
}

__global__ void __launch_bounds__(256)
stageC_kernel(const float* __restrict__ U, float* __restrict__ out)
{
    __shared__ float w0s[K_],w1s[K_],u0s[64],u1s[64];
    const int s=blockIdx.y, n0=blockIdx.x*64, tid=threadIdx.x;
    w0s[tid]=g_w[(s*K_+tid)*2];
    w1s[tid]=g_w[(s*K_+tid)*2+1];
    if(tid<64){
        const float* up=U+((size_t)(s*N_+n0+tid)<<1);
        u0s[tid]=up[0]; u1s[tid]=up[1];
    }
    __syncthreads();
    const int kq=tid&63, r=tid>>6;
    #pragma unroll
    for(int nn=0;nn<16;++nn){
        int nl=nn*4+r;
        float u0=u0s[nl],u1=u1s[nl];
        int k=kq*4;
        float4 o;
        o.x=fmaxf(fmaf(u0,w0s[k],u1*w1s[k]),0.f);
        o.y=fmaxf(fmaf(u0,w0s[k+1],u1*w1s[k+1]),0.f);
        o.z=fmaxf(fmaf(u0,w0s[k+2],u1*w1s[k+2]),0.f);
        o.w=fmaxf(fmaf(u0,w0s[k+3],u1*w1s[k+3]),0.f);
        reinterpret_cast<float4*>(out)[(((size_t)(s*N_+n0+nl))*K_+k)>>2]=o;
    }
}

extern "C" void kernel_launch(void* const* d_in, const int* in_sizes, int n_in,
                              void* d_out, int out_size)
{
    const float* U  =(const float*)d_in[0];
    const float* eps=(const float*)d_in[1];
    const float* W1 =(const float*)d_in[2];
    const float* b1 =(const float*)d_in[3];
    const float* W2 =(const float*)d_in[4];
    const float* b2 =(const float*)d_in[5];
    const float* W3 =(const float*)d_in[6];
    const float* b3 =(const float*)d_in[7];
    float* out=(float*)d_out;

    cudaFuncSetAttribute((const void*)stageA_kernel,
                         cudaFuncAttributeMaxDynamicSharedMemorySize, SMEM_TOTAL);
    round_kernel<<<(H_*2*K_+255)/256,256>>>(W2,W3);
    stageA_kernel<<<dim3(NB,S_),NT,SMEM_TOTAL>>>(U,W1,b1,b2,b3);
    stageB_kernel<<<S_,1024>>>(eps, out+(out_size-S_));
    stageC_kernel<<<dim3(N_/64,S_),256>>>(U,out);
}

// round 14
// speedup vs baseline: 1.2775x; 1.2775x over previous
#include <cuda_runtime.h>
#include <mma.h>
#include <cstdint>
using namespace nvcuda;

#define S_ 4
#define N_ 32768
#define K_ 256
#define H_ 100
#define NB 256
#define NBW 2048
#define NT 256
#define SA 108
#define SW2 116

#define OFF_HS 0
#define OFF_B  55296
#define OFF_SC (OFF_B+29952)
#define OFF_US (OFF_SC+16384)
#define OFF_B2 (OFF_US+1024)
#define OFF_B3 (OFF_B2+448)
#define SMEM_TOTAL (OFF_B3+2048)

__device__ float g_part[(size_t)S_*5*NBW*K_];
__device__ float g_w[S_*K_*2];

static __device__ __forceinline__ unsigned smem_u32(const void* p){
    return (unsigned)__cvta_generic_to_shared(p);
}
static __device__ __forceinline__ void cpa16(unsigned dst, const float* src){
    asm volatile("cp.async.cg.shared.global [%0], [%1], 16;\n" :: "r"(dst), "l"(src));
}
#define CPA_COMMIT() asm volatile("cp.async.commit_group;\n" ::: "memory")
#define CPA_WAIT0()  asm volatile("cp.async.wait_group 0;\n" ::: "memory")

typedef wmma::fragment<wmma::matrix_a,16,16,8,wmma::precision::tf32,wmma::row_major> FragA;
typedef wmma::fragment<wmma::matrix_b,16,16,8,wmma::precision::tf32,wmma::row_major> FragB;
typedef wmma::fragment<wmma::accumulator,16,16,8,float> FragC;

// load raw fp32 B tile, split hi/lo in registers, 2 MMAs (R10-proven)
static __device__ __forceinline__ void mma_split(FragC& fc, const FragA& fa,
                                                 const float* bp, int ldm){
    FragB fbh, fbl;
    wmma::load_matrix_sync(fbh, bp, ldm);
    #pragma unroll
    for(int i=0;i<fbh.num_elements;++i){
        float v = fbh.x[i];
        fbh.x[i] = wmma::__float_to_tf32(v);
        fbl.x[i] = wmma::__float_to_tf32(v - fbh.x[i]);
    }
    wmma::mma_sync(fc, fa, fbh, fc);
    wmma::mma_sync(fc, fa, fbl, fc);
}

// stage W3 chunk c (raw): LP cols c*32.. -> buf cols 0..31, MU cols 256+c*32.. -> 32..63
static __device__ __forceinline__ void stage3(float* B, const float* W3, int c, int tid){
    for(int idx=tid; idx<1600; idx+=NT){
        int r=idx>>4, t=idx&15, mu=t>>3, sg=t&7;
        cpa16(smem_u32(B + r*72 + mu*32 + sg*4), W3 + (size_t)r*512 + mu*256 + c*32 + sg*4);
    }
}

__global__ void __launch_bounds__(NT,2)
stageA_kernel(const float* __restrict__ U,  const float* __restrict__ W1,
              const float* __restrict__ b1, const float* __restrict__ W2,
              const float* __restrict__ b2, const float* __restrict__ W3,
              const float* __restrict__ b3)
{
    extern __shared__ char smc[];
    float* hS =(float*)(smc+OFF_HS);
    float* Bf =(float*)(smc+OFF_B);
    float* SC =(float*)(smc+OFF_SC);
    float* uS =(float*)(smc+OFF_US);
    float* b2S=(float*)(smc+OFF_B2);
    float* b3S=(float*)(smc+OFF_B3);
    const int tid=threadIdx.x, w=tid>>5, lid=tid&31;
    const int s=blockIdx.y, blk=blockIdx.x;
    float* sc = SC + w*512;

    // zero pad rows 100..103 of the chunk layout (floats 7200..7487); never rewritten
    for(int i=tid;i<288;i+=NT) Bf[7200+i]=0.f;
    if(tid<128){
        const float* up=U+((size_t)(s*N_+blk*128+tid)<<1);
        uS[tid]=up[0]; uS[128+tid]=up[1];
    }
    if(tid<112) b2S[tid]=(tid<H_)?b2[tid]:0.f;
    for(int i=tid;i<512;i+=NT) b3S[i]=b3[i];

    // stage W2 half0: rows 0..55 (raw); zero cols 100..115
    for(int idx=tid; idx<56*25; idx+=NT){
        int r=idx/25, sg=idx-r*25;
        cpa16(smem_u32(Bf + r*SW2 + sg*4), W2 + r*H_ + sg*4);
    }
    for(int idx=tid; idx<56*4; idx+=NT){
        int r=idx>>2, sg=idx&3;
        *reinterpret_cast<float4*>(Bf + r*SW2 + 100 + sg*4)=make_float4(0,0,0,0);
    }
    CPA_COMMIT();
    __syncthreads();

    // h1 = relu(U@W1+b1), tf32-rounded; cols 100..103 zero
    for(int idx=tid;idx<128*104;idx+=NT){
        int m=idx/104, i=idx-m*104;
        float v=(i<H_)?fmaxf(fmaf(uS[m],W1[i],fmaf(uS[128+m],W1[H_+i],b1[i])),0.f):0.f;
        hS[m*SA+i]=wmma::__float_to_tf32(v);
    }
    CPA_WAIT0(); __syncthreads();

    // ---- GEMM2, two k-halves over single buffer ----
    {
        FragA fa; FragC fc[7];
        #pragma unroll
        for(int t=0;t<7;++t) wmma::fill_fragment(fc[t],0.f);
        for(int k=0;k<7;++k){
            wmma::load_matrix_sync(fa, hS+(w*16)*SA+k*8, SA);
            #pragma unroll
            for(int t=0;t<7;++t) mma_split(fc[t], fa, Bf+k*8*SW2+t*16, SW2);
        }
        __syncthreads();
        // stage half1: W2 rows 56..99 -> buf rows 0..43; zero rows 44..47 fully; zero col-pad
        for(int idx=tid; idx<44*25; idx+=NT){
            int r=idx/25, sg=idx-r*25;
            cpa16(smem_u32(Bf + r*SW2 + sg*4), W2 + (56+r)*H_ + sg*4);
        }
        for(int idx=tid; idx<44*4; idx+=NT){
            int r=idx>>2, sg=idx&3;
            *reinterpret_cast<float4*>(Bf + r*SW2 + 100 + sg*4)=make_float4(0,0,0,0);
        }
        for(int idx=tid; idx<4*29; idx+=NT){
            int r=44+idx/29, sg=idx%29;
            *reinterpret_cast<float4*>(Bf + r*SW2 + sg*4)=make_float4(0,0,0,0);
        }
        CPA_COMMIT(); CPA_WAIT0(); __syncthreads();
        for(int k=7;k<13;++k){
            wmma::load_matrix_sync(fa, hS+(w*16)*SA+k*8, SA);
            #pragma unroll
            for(int t=0;t<7;++t) mma_split(fc[t], fa, Bf+(k-7)*8*SW2+t*16, SW2);
        }
        // h2 writeback (warp-private rows)
        #pragma unroll
        for(int t=0;t<7;++t){
            wmma::store_matrix_sync(sc, fc[t], 16, wmma::mem_row_major);
            __syncwarp();
            for(int e2=lid;e2<256;e2+=32){
                int r=e2>>4, c2=e2&15, j=t*16+c2;
                if(j<104) hS[(w*16+r)*SA+j]=wmma::__float_to_tf32(fmaxf(sc[e2]+b2S[j],0.f));
            }
            __syncwarp();
        }
    }
    __syncthreads();

    // ---- GEMM3: 8 chunks of (32 LP + 32 MU) cols; stage(c+1) overlaps epilogue(c) ----
    stage3(Bf, W3, 0, tid); CPA_COMMIT(); CPA_WAIT0(); __syncthreads();
    for(int c=0;c<8;++c){
        FragA fa; FragC fL[2], fM[2];
        #pragma unroll
        for(int t=0;t<2;++t){ wmma::fill_fragment(fL[t],0.f); wmma::fill_fragment(fM[t],0.f); }
        for(int k=0;k<13;++k){
            wmma::load_matrix_sync(fa, hS+(w*16)*SA+k*8, SA);
            #pragma unroll
            for(int t=0;t<2;++t){
                mma_split(fL[t], fa, Bf+k*8*72+t*16, 72);
                mma_split(fM[t], fa, Bf+k*8*72+32+t*16, 72);
            }
        }
        __syncthreads();                       // buffer reads done
        if(c<7){ stage3(Bf, W3, c+1, tid); CPA_COMMIT(); }
        // epilogue (R13-proven): exp + 5 reductions, per-warp partials to g_part
        #pragma unroll
        for(int t=0;t<2;++t){
            wmma::store_matrix_sync(sc,     fL[t], 16, wmma::mem_row_major);
            wmma::store_matrix_sync(sc+256, fM[t], 16, wmma::mem_row_major);
            __syncwarp();
            int col=lid&15, rh=lid>>4;
            int kg=c*32+t*16+col;
            float bl=b3S[kg], bm=b3S[256+kg];
            float a=0,b=0,cc=0,d=0,e=0;
            #pragma unroll
            for(int r8=0;r8<8;++r8){
                int r=rh*8+r8, gr=w*16+r;
                float u0=uS[gr], u1=uS[128+gr];
                float p =__expf(sc[r*16+col]+bl);
                float pm=p*(sc[256+r*16+col]+bm);
                a+=p*u0*u0; b+=p*u0*u1; cc+=p*u1*u1; d+=pm*u0; e+=pm*u1;
            }
            a+=__shfl_xor_sync(0xffffffffu,a,16);
            b+=__shfl_xor_sync(0xffffffffu,b,16);
            cc+=__shfl_xor_sync(0xffffffffu,cc,16);
            d+=__shfl_xor_sync(0xffffffffu,d,16);
            e+=__shfl_xor_sync(0xffffffffu,e,16);
            if(lid<16){
                size_t base=(((size_t)s*5)*NBW+(size_t)(blk*8+w))*K_ + kg;
                const size_t cs=(size_t)NBW*K_;
                g_part[base]=a; g_part[base+cs]=b; g_part[base+2*cs]=cc;
                g_part[base+3*cs]=d; g_part[base+4*cs]=e;
            }
            __syncwarp();
        }
        if(c<7){ CPA_WAIT0(); __syncthreads(); }
    }
}

__global__ void __launch_bounds__(1024) stageB_kernel(const float* __restrict__ eps,
                                                      float* __restrict__ kl_out)
{
    __shared__ float sm5[5][4][K_];
    __shared__ float red[K_];
    const int s=blockIdx.x, tid=threadIdx.x, k=tid&255, q=tid>>8;
    const float* base=g_part+((size_t)s*5*NBW)*K_+k;
    const size_t cs=(size_t)NBW*K_;
    float A=0,B=0,C=0,dd=0,ee=0;
    for(int b=q*512;b<q*512+512;++b){
        size_t o=(size_t)b*K_;
        A+=base[o]; B+=base[cs+o]; C+=base[2*cs+o]; dd+=base[3*cs+o]; ee+=base[4*cs+o];
    }
    sm5[0][q][k]=A; sm5[1][q][k]=B; sm5[2][q][k]=C; sm5[3][q][k]=dd; sm5[4][q][k]=ee;
    __syncthreads();
    if(q==0){
        A =sm5[0][0][k]+sm5[0][1][k]+sm5[0][2][k]+sm5[0][3][k]+1.f;
        B =sm5[1][0][k]+sm5[1][1][k]+sm5[1][2][k]+sm5[1][3][k];
        C =sm5[2][0][k]+sm5[2][1][k]+sm5[2][2][k]+sm5[2][3][k]+1.f;
        dd=sm5[3][0][k]+sm5[3][1][k]+sm5[3][2][k]+sm5[3][3][k];
        ee=sm5[4][0][k]+sm5[4][1][k]+sm5[4][2][k]+sm5[4][3][k];
        float det=A*C-B*B, inv=1.f/det;
        float c00=C*inv, c01=-B*inv, c11=A*inv;
        float qm0=c00*dd+c01*ee, qm1=c01*dd+c11*ee;
        float l00=sqrtf(c00), l10=c01/l00, l11=sqrtf(fmaxf(c11-l10*l10,0.f));
        float e0=eps[(s*K_+k)*2], e1=eps[(s*K_+k)*2+1];
        g_w[(s*K_+k)*2]  =qm0+l00*e0;
        g_w[(s*K_+k)*2+1]=qm1+l10*e0+l11*e1;
        red[k]=0.5f*((c00+c11)+(qm0*qm0+qm1*qm1)-2.f+logf(det));
    }
    __syncthreads();
    for(int off=128;off;off>>=1){
        if(tid<off) red[tid]+=red[tid+off];
        __syncthreads();
    }
    if(tid==0) kl_out[s]=red[0];
}

__global__ void __launch_bounds__(256)
stageC_kernel(const float* __restrict__ U, float* __restrict__ out)
{
    __shared__ float w0s[K_],w1s[K_],u0s[64],u1s[64];
    const int s=blockIdx.y, n0=blockIdx.x*64, tid=threadIdx.x;
    w0s[tid]=g_w[(s*K_+tid)*2];
    w1s[tid]=g_w[(s*K_+tid)*2+1];
    if(tid<64){
        const float* up=U+((size_t)(s*N_+n0+tid)<<1);
        u0s[tid]=up[0]; u1s[tid]=up[1];
    }
    __syncthreads();
    const int kq=tid&63, r=tid>>6;
    #pragma unroll
    for(int nn=0;nn<16;++nn){
        int nl=nn*4+r;
        float u0=u0s[nl],u1=u1s[nl];
        int k=kq*4;
        float4 o;
        o.x=fmaxf(fmaf(u0,w0s[k],u1*w1s[k]),0.f);
        o.y=fmaxf(fmaf(u0,w0s[k+1],u1*w1s[k+1]),0.f);
        o.z=fmaxf(fmaf(u0,w0s[k+2],u1*w1s[k+2]),0.f);
        o.w=fmaxf(fmaf(u0,w0s[k+3],u1*w1s[k+3]),0.f);
        reinterpret_cast<float4*>(out)[(((size_t)(s*N_+n0+nl))*K_+k)>>2]=o;
    }
}

extern "C" void kernel_launch(void* const* d_in, const int* in_sizes, int n_in,
                              void* d_out, int out_size)
{
    const float* U  =(const float*)d_in[0];
    const float* eps=(const float*)d_in[1];
    const float* W1 =(const float*)d_in[2];
    const float* b1 =(const float*)d_in[3];
    const float* W2 =(const float*)d_in[4];
    const float* b2 =(const float*)d_in[5];
    const float* W3 =(const float*)d_in[6];
    const float* b3 =(const float*)d_in[7];
    float* out=(float*)d_out;

    cudaFuncSetAttribute((const void*)stageA_kernel,
                         cudaFuncAttributeMaxDynamicSharedMemorySize, SMEM_TOTAL);
    stageA_kernel<<<dim3(NB,S_),NT,SMEM_TOTAL>>>(U,W1,b1,W2,b2,W3,b3);
    stageB_kernel<<<S_,1024>>>(eps, out+(out_size-S_));
    stageC_kernel<<<dim3(N_/64,S_),256>>>(U,out);
}

// round 15
// speedup vs baseline: 2.0616x; 1.6137x over previous
#include <cuda_runtime.h>
#include <cuda_bf16.h>
#include <mma.h>
#include <cstdint>
using namespace nvcuda;

#define S_ 4
#define N_ 32768
#define K_ 256
#define H_ 100
#define NB 256
#define NBW 2048
#define NT 256
#define SAH 112          // hS stride (bf16 elements)
#define SB2 112          // GEMM2 B stride (elements)
#define SB3E 72          // GEMM3 B stride (elements)

#define OFF_HS 0
#define OFF_B  28672
#define OFF_SC 60928
#define OFF_US 77312
#define OFF_B2 78336
#define OFF_B3 78784
#define SMEM_TOTAL (OFF_B3+2048)

__device__ __nv_bfloat16 g_w2h[H_*112], g_w2l[H_*112];   // padded cols 100..111 = 0
__device__ __nv_bfloat16 g_w3h[H_*512], g_w3l[H_*512];
__device__ float g_part[(size_t)S_*5*NBW*K_];
__device__ float g_w[S_*K_*2];

static __device__ __forceinline__ unsigned smem_u32(const void* p){
    return (unsigned)__cvta_generic_to_shared(p);
}
static __device__ __forceinline__ void cpa16(unsigned dst, const void* src){
    asm volatile("cp.async.cg.shared.global [%0], [%1], 16;\n" :: "r"(dst), "l"(src));
}
#define CPA_COMMIT() asm volatile("cp.async.commit_group;\n" ::: "memory")
#define CPA_WAIT0()  asm volatile("cp.async.wait_group 0;\n" ::: "memory")

typedef wmma::fragment<wmma::matrix_a,16,16,16,__nv_bfloat16,wmma::row_major> FragA;
typedef wmma::fragment<wmma::matrix_b,16,16,16,__nv_bfloat16,wmma::row_major> FragB;
typedef wmma::fragment<wmma::accumulator,16,16,16,float> FragC;

__global__ void round_kernel(const float* __restrict__ W2, const float* __restrict__ W3){
    int i = blockIdx.x*256 + threadIdx.x;
    if(i < H_*112){
        int r=i/112, c=i-r*112;
        float v = (c<H_)? W2[r*H_+c] : 0.f;
        __nv_bfloat16 h=__float2bfloat16(v);
        g_w2h[i]=h; g_w2l[i]=__float2bfloat16(v-__bfloat162float(h));
    }
    if(i < H_*512){
        float v=W3[i];
        __nv_bfloat16 h=__float2bfloat16(v);
        g_w3h[i]=h; g_w3l[i]=__float2bfloat16(v-__bfloat162float(h));
    }
}

// stage W3 chunk c: LP cols c*32.. -> cols 0..31, MU cols 256+c*32.. -> cols 32..63 (hi & lo)
static __device__ __forceinline__ void stage3(__nv_bfloat16* Bb, int c, int tid){
    for(int idx=tid; idx<1600; idx+=NT){
        int part = idx>=800, j = part? idx-800 : idx;
        int r=j>>3, t=j&7, mu=t>>2, sg=t&3;
        const __nv_bfloat16* src = (part? g_w3l : g_w3h) + (size_t)r*512 + mu*256 + c*32 + sg*8;
        cpa16(smem_u32(Bb + part*(112*SB3E) + r*SB3E + mu*32 + sg*8), src);
    }
}
// stage W2 rows r0..r0+rn-1 into buffer rows 0..rn-1 (hi & lo, 14x8 cols = 112)
static __device__ __forceinline__ void stage_w2(__nv_bfloat16* Bb, int r0, int rn, int tid){
    for(int idx=tid; idx<2*rn*14; idx+=NT){
        int part = idx>=rn*14, j = part? idx-rn*14 : idx;
        int r=j/14, u=j-r*14;
        const __nv_bfloat16* src = (part? g_w2l : g_w2h) + (r0+r)*112 + u*8;
        cpa16(smem_u32(Bb + part*(64*SB2) + r*SB2 + u*8), src);
    }
}

__global__ void __launch_bounds__(NT,2)
stageA_kernel(const float* __restrict__ U,  const float* __restrict__ W1,
              const float* __restrict__ b1, const float* __restrict__ b2,
              const float* __restrict__ b3)
{
    extern __shared__ char smc[];
    __nv_bfloat16* hS =(__nv_bfloat16*)(smc+OFF_HS);
    __nv_bfloat16* Bb =(__nv_bfloat16*)(smc+OFF_B);
    float* SC =(float*)(smc+OFF_SC);
    float* uS =(float*)(smc+OFF_US);
    float* b2S=(float*)(smc+OFF_B2);
    float* b3S=(float*)(smc+OFF_B3);
    const int tid=threadIdx.x, w=tid>>5, lid=tid&31;
    const int s=blockIdx.y, blk=blockIdx.x;
    float* sc = SC + w*512;

    if(tid<128){
        const float* up=U+((size_t)(s*N_+blk*128+tid)<<1);
        uS[tid]=up[0]; uS[128+tid]=up[1];
    }
    if(tid<112) b2S[tid]=(tid<H_)?b2[tid]:0.f;
    for(int i=tid;i<512;i+=NT) b3S[i]=b3[i];

    stage_w2(Bb, 0, 64, tid);     // half0: rows 0..63  [group 1]
    CPA_COMMIT();
    __syncthreads();

    // h1 = relu(U@W1+b1) -> bf16; cols 100..111 zero
    for(int idx=tid;idx<128*112;idx+=NT){
        int m=idx/112, i=idx-m*112;
        float v=(i<H_)?fmaxf(fmaf(uS[m],W1[i],fmaf(uS[128+m],W1[H_+i],b1[i])),0.f):0.f;
        hS[m*SAH+i]=__float2bfloat16(v);
    }
    CPA_WAIT0(); __syncthreads();

    // ---- GEMM2: 7 n-tiles, hi+lo bf16, k = 7x16 in two halves ----
    {
        __nv_bfloat16* Bh=Bb; __nv_bfloat16* Bl=Bb+64*SB2;
        FragA fa; FragB fb; FragC fc[7];
        #pragma unroll
        for(int t=0;t<7;++t) wmma::fill_fragment(fc[t],0.f);
        for(int k=0;k<4;++k){
            wmma::load_matrix_sync(fa, hS+(w*16)*SAH+k*16, SAH);
            #pragma unroll
            for(int t=0;t<7;++t){
                wmma::load_matrix_sync(fb, Bh+k*16*SB2+t*16, SB2); wmma::mma_sync(fc[t],fa,fb,fc[t]);
                wmma::load_matrix_sync(fb, Bl+k*16*SB2+t*16, SB2); wmma::mma_sync(fc[t],fa,fb,fc[t]);
            }
        }
        __syncthreads();
        stage_w2(Bb, 64, 36, tid);          // half1: rows 64..99 -> buf rows 0..35
        // zero buf rows 36..47 (both parts)
        for(int i=tid;i<2*672;i+=NT){
            int part=i>=672, j=part? i-672:i;
            ((uint32_t*)(Bb+part*(64*SB2)))[2016+j]=0u;
        }
        CPA_COMMIT(); CPA_WAIT0(); __syncthreads();
        for(int k=4;k<7;++k){
            wmma::load_matrix_sync(fa, hS+(w*16)*SAH+k*16, SAH);
            #pragma unroll
            for(int t=0;t<7;++t){
                wmma::load_matrix_sync(fb, Bh+(k-4)*16*SB2+t*16, SB2); wmma::mma_sync(fc[t],fa,fb,fc[t]);
                wmma::load_matrix_sync(fb, Bl+(k-4)*16*SB2+t*16, SB2); wmma::mma_sync(fc[t],fa,fb,fc[t]);
            }
        }
        // h2 writeback (warp-private rows); cols 100..111 auto-zero (pad weights+bias)
        #pragma unroll
        for(int t=0;t<7;++t){
            wmma::store_matrix_sync(sc, fc[t], 16, wmma::mem_row_major);
            __syncwarp();
            for(int e2=lid;e2<256;e2+=32){
                int r=e2>>4, c2=e2&15, j=t*16+c2;
                hS[(w*16+r)*SAH+j]=__float2bfloat16(fmaxf(sc[e2]+b2S[j],0.f));
            }
            __syncwarp();
        }
    }
    __syncthreads();

    // ---- GEMM3: 8 chunks of (32 LP + 32 MU); rows 100..111 of B zeroed once ----
    for(int i=tid;i<2*432;i+=NT){
        int part=i>=432, j=part? i-432:i;
        ((uint32_t*)(Bb+part*(112*SB3E)))[3600+j]=0u;   // elements 7200..8063
    }
    stage3(Bb, 0, tid); CPA_COMMIT(); CPA_WAIT0(); __syncthreads();
    __nv_bfloat16* B3h=Bb; __nv_bfloat16* B3l=Bb+112*SB3E;
    for(int c=0;c<8;++c){
        FragA fa; FragB fb; FragC fL[2], fM[2];
        #pragma unroll
        for(int t=0;t<2;++t){ wmma::fill_fragment(fL[t],0.f); wmma::fill_fragment(fM[t],0.f); }
        for(int k=0;k<7;++k){
            wmma::load_matrix_sync(fa, hS+(w*16)*SAH+k*16, SAH);
            #pragma unroll
            for(int t=0;t<2;++t){
                wmma::load_matrix_sync(fb, B3h+k*16*SB3E+t*16, SB3E);    wmma::mma_sync(fL[t],fa,fb,fL[t]);
                wmma::load_matrix_sync(fb, B3l+k*16*SB3E+t*16, SB3E);    wmma::mma_sync(fL[t],fa,fb,fL[t]);
                wmma::load_matrix_sync(fb, B3h+k*16*SB3E+32+t*16, SB3E); wmma::mma_sync(fM[t],fa,fb,fM[t]);
                wmma::load_matrix_sync(fb, B3l+k*16*SB3E+32+t*16, SB3E); wmma::mma_sync(fM[t],fa,fb,fM[t]);
            }
        }
        __syncthreads();                       // buffer reads done
        if(c<7){ stage3(Bb, c+1, tid); CPA_COMMIT(); }
        // epilogue: exp + 5 reductions over 16 rows, per-warp partials
        #pragma unroll
        for(int t=0;t<2;++t){
            wmma::store_matrix_sync(sc,     fL[t], 16, wmma::mem_row_major);
            wmma::store_matrix_sync(sc+256, fM[t], 16, wmma::mem_row_major);
            __syncwarp();
            int col=lid&15, rh=lid>>4;
            int kg=c*32+t*16+col;
            float bl=b3S[kg], bm=b3S[256+kg];
            float a=0,b=0,cc=0,d=0,e=0;
            #pragma unroll
            for(int r8=0;r8<8;++r8){
                int r=rh*8+r8, gr=w*16+r;
                float u0=uS[gr], u1=uS[128+gr];
                float p =__expf(sc[r*16+col]+bl);
                float pm=p*(sc[256+r*16+col]+bm);
                a+=p*u0*u0; b+=p*u0*u1; cc+=p*u1*u1; d+=pm*u0; e+=pm*u1;
            }
            a+=__shfl_xor_sync(0xffffffffu,a,16);
            b+=__shfl_xor_sync(0xffffffffu,b,16);
            cc+=__shfl_xor_sync(0xffffffffu,cc,16);
            d+=__shfl_xor_sync(0xffffffffu,d,16);
            e+=__shfl_xor_sync(0xffffffffu,e,16);
            if(lid<16){
                size_t base=(((size_t)s*5)*NBW+(size_t)(blk*8+w))*K_ + kg;
                const size_t cs=(size_t)NBW*K_;
                g_part[base]=a; g_part[base+cs]=b; g_part[base+2*cs]=cc;
                g_part[base+3*cs]=d; g_part[base+4*cs]=e;
            }
            __syncwarp();
        }
        if(c<7){ CPA_WAIT0(); __syncthreads(); }
    }
}

__global__ void __launch_bounds__(1024) stageB_kernel(const float* __restrict__ eps,
                                                      float* __restrict__ kl_out)
{
    __shared__ float sm5[5][4][K_];
    __shared__ float red[K_];
    const int s=blockIdx.x, tid=threadIdx.x, k=tid&255, q=tid>>8;
    const float* base=g_part+((size_t)s*5*NBW)*K_+k;
    const size_t cs=(size_t)NBW*K_;
    float A=0,B=0,C=0,dd=0,ee=0;
    for(int b=q*512;b<q*512+512;++b){
        size_t o=(size_t)b*K_;
        A+=base[o]; B+=base[cs+o]; C+=base[2*cs+o]; dd+=base[3*cs+o]; ee+=base[4*cs+o];
    }
    sm5[0][q][k]=A; sm5[1][q][k]=B; sm5[2][q][k]=C; sm5[3][q][k]=dd; sm5[4][q][k]=ee;
    __syncthreads();
    if(q==0){
        A =sm5[0][0][k]+sm5[0][1][k]+sm5[0][2][k]+sm5[0][3][k]+1.f;
        B =sm5[1][0][k]+sm5[1][1][k]+sm5[1][2][k]+sm5[1][3][k];
        C =sm5[2][0][k]+sm5[2][1][k]+sm5[2][2][k]+sm5[2][3][k]+1.f;
        dd=sm5[3][0][k]+sm5[3][1][k]+sm5[3][2][k]+sm5[3][3][k];
        ee=sm5[4][0][k]+sm5[4][1][k]+sm5[4][2][k]+sm5[4][3][k];
        float det=A*C-B*B, inv=1.f/det;
        float c00=C*inv, c01=-B*inv, c11=A*inv;
        float qm0=c00*dd+c01*ee, qm1=c01*dd+c11*ee;
        float l00=sqrtf(c00), l10=c01/l00, l11=sqrtf(fmaxf(c11-l10*l10,0.f));
        float e0=eps[(s*K_+k)*2], e1=eps[(s*K_+k)*2+1];
        g_w[(s*K_+k)*2]  =qm0+l00*e0;
        g_w[(s*K_+k)*2+1]=qm1+l10*e0+l11*e1;
        red[k]=0.5f*((c00+c11)+(qm0*qm0+qm1*qm1)-2.f+logf(det));
    }
    __syncthreads();
    for(int off=128;off;off>>=1){
        if(tid<off) red[tid]+=red[tid+off];
        __syncthreads();
    }
    if(tid==0) kl_out[s]=red[0];
}

__global__ void __launch_bounds__(256)
stageC_kernel(const float* __restrict__ U, float* __restrict__ out)
{
    __shared__ float w0s[K_],w1s[K_],u0s[64],u1s[64];
    const int s=blockIdx.y, n0=blockIdx.x*64, tid=threadIdx.x;
    w0s[tid]=g_w[(s*K_+tid)*2];
    w1s[tid]=g_w[(s*K_+tid)*2+1];
    if(tid<64){
        const float* up=U+((size_t)(s*N_+n0+tid)<<1);
        u0s[tid]=up[0]; u1s[tid]=up[1];
    }
    __syncthreads();
    const int kq=tid&63, r=tid>>6;
    #pragma unroll
    for(int nn=0;nn<16;++nn){
        int nl=nn*4+r;
        float u0=u0s[nl],u1=u1s[nl];
        int k=kq*4;
        float4 o;
        o.x=fmaxf(fmaf(u0,w0s[k],u1*w1s[k]),0.f);
        o.y=fmaxf(fmaf(u0,w0s[k+1],u1*w1s[k+1]),0.f);
        o.z=fmaxf(fmaf(u0,w0s[k+2],u1*w1s[k+2]),0.f);
        o.w=fmaxf(fmaf(u0,w0s[k+3],u1*w1s[k+3]),0.f);
        reinterpret_cast<float4*>(out)[(((size_t)(s*N_+n0+nl))*K_+k)>>2]=o;
    }
}

extern "C" void kernel_launch(void* const* d_in, const int* in_sizes, int n_in,
                              void* d_out, int out_size)
{
    const float* U  =(const float*)d_in[0];
    const float* eps=(const float*)d_in[1];
    const float* W1 =(const float*)d_in[2];
    const float* b1 =(const float*)d_in[3];
    const float* W2 =(const float*)d_in[4];
    const float* b2 =(const float*)d_in[5];
    const float* W3 =(const float*)d_in[6];
    const float* b3 =(const float*)d_in[7];
    float* out=(float*)d_out;

    cudaFuncSetAttribute((const void*)stageA_kernel,
                         cudaFuncAttributeMaxDynamicSharedMemorySize, SMEM_TOTAL);
    round_kernel<<<(H_*512+255)/256,256>>>(W2,W3);
    stageA_kernel<<<dim3(NB,S_),NT,SMEM_TOTAL>>>(U,W1,b1,b2,b3);
    stageB_kernel<<<S_,1024>>>(eps, out+(out_size-S_));
    stageC_kernel<<<dim3(N_/64,S_),256>>>(U,out);
}

// round 16
// speedup vs baseline: 2.1065x; 1.0218x over previous
#include <cuda_runtime.h>
#include <cuda_bf16.h>
#include <mma.h>
#include <cstdint>
using namespace nvcuda;

#define S_ 4
#define N_ 32768
#define K_ 256
#define H_ 100
#define NB 256
#define NBW 2048
#define NT 256
#define SAH 112          // hS stride (bf16 elements)
#define SB2 112          // GEMM2 B stride (elements)
#define SB3E 72          // GEMM3 B stride (elements)

#define OFF_HS 0
#define OFF_B  28672
#define OFF_SC 60928
#define OFF_US 77312
#define OFF_B2 78336
#define OFF_B3 78784
#define SMEM_TOTAL (OFF_B3+2048)

__device__ __nv_bfloat16 g_w2h[H_*112], g_w2l[H_*112];   // padded cols 100..111 = 0
__device__ __nv_bfloat16 g_w3h[H_*512], g_w3l[H_*512];
__device__ float g_part[(size_t)S_*5*NBW*K_];
__device__ float g_w[S_*K_*2];

static __device__ __forceinline__ unsigned smem_u32(const void* p){
    return (unsigned)__cvta_generic_to_shared(p);
}
static __device__ __forceinline__ void cpa16(unsigned dst, const void* src){
    asm volatile("cp.async.cg.shared.global [%0], [%1], 16;\n" :: "r"(dst), "l"(src));
}
#define CPA_COMMIT() asm volatile("cp.async.commit_group;\n" ::: "memory")
#define CPA_WAIT0()  asm volatile("cp.async.wait_group 0;\n" ::: "memory")

typedef wmma::fragment<wmma::matrix_a,16,16,16,__nv_bfloat16,wmma::row_major> FragA;
typedef wmma::fragment<wmma::matrix_b,16,16,16,__nv_bfloat16,wmma::row_major> FragB;
typedef wmma::fragment<wmma::accumulator,16,16,16,float> FragC;

__global__ void round_kernel(const float* __restrict__ W2, const float* __restrict__ W3){
    int i = blockIdx.x*256 + threadIdx.x;
    if(i < H_*112){
        int r=i/112, c=i-r*112;
        float v = (c<H_)? W2[r*H_+c] : 0.f;
        __nv_bfloat16 h=__float2bfloat16(v);
        g_w2h[i]=h; g_w2l[i]=__float2bfloat16(v-__bfloat162float(h));
    }
    if(i < H_*512){
        float v=W3[i];
        __nv_bfloat16 h=__float2bfloat16(v);
        g_w3h[i]=h; g_w3l[i]=__float2bfloat16(v-__bfloat162float(h));
    }
}

// stage W3 chunk c: LP cols c*32.. -> cols 0..31, MU cols 256+c*32.. -> cols 32..63 (hi & lo)
static __device__ __forceinline__ void stage3(__nv_bfloat16* Bb, int c, int tid){
    for(int idx=tid; idx<1600; idx+=NT){
        int part = idx>=800, j = part? idx-800 : idx;
        int r=j>>3, t=j&7, mu=t>>2, sg=t&3;
        const __nv_bfloat16* src = (part? g_w3l : g_w3h) + (size_t)r*512 + mu*256 + c*32 + sg*8;
        cpa16(smem_u32(Bb + part*(112*SB3E) + r*SB3E + mu*32 + sg*8), src);
    }
}
// stage W2 rows r0..r0+rn-1 into buffer rows 0..rn-1 (hi & lo, 14x8 cols = 112)
static __device__ __forceinline__ void stage_w2(__nv_bfloat16* Bb, int r0, int rn, int tid){
    for(int idx=tid; idx<2*rn*14; idx+=NT){
        int part = idx>=rn*14, j = part? idx-rn*14 : idx;
        int r=j/14, u=j-r*14;
        const __nv_bfloat16* src = (part? g_w2l : g_w2h) + (r0+r)*112 + u*8;
        cpa16(smem_u32(Bb + part*(64*SB2) + r*SB2 + u*8), src);
    }
}

__global__ void __launch_bounds__(NT,2)
stageA_kernel(const float* __restrict__ U,  const float* __restrict__ W1,
              const float* __restrict__ b1, const float* __restrict__ b2,
              const float* __restrict__ b3)
{
    extern __shared__ char smc[];
    __nv_bfloat16* hS =(__nv_bfloat16*)(smc+OFF_HS);
    __nv_bfloat16* Bb =(__nv_bfloat16*)(smc+OFF_B);
    float* SC =(float*)(smc+OFF_SC);
    float* uS =(float*)(smc+OFF_US);
    float* b2S=(float*)(smc+OFF_B2);
    float* b3S=(float*)(smc+OFF_B3);
    const int tid=threadIdx.x, w=tid>>5, lid=tid&31;
    const int s=blockIdx.y, blk=blockIdx.x;
    float* sc = SC + w*512;

    if(tid<128){
        const float* up=U+((size_t)(s*N_+blk*128+tid)<<1);
        uS[tid]=up[0]; uS[128+tid]=up[1];
    }
    if(tid<112) b2S[tid]=(tid<H_)?b2[tid]:0.f;
    for(int i=tid;i<512;i+=NT) b3S[i]=b3[i];

    stage_w2(Bb, 0, 64, tid);     // half0: rows 0..63  [group 1]
    CPA_COMMIT();
    __syncthreads();

    // h1 = relu(U@W1+b1) -> bf16; cols 100..111 zero
    for(int idx=tid;idx<128*112;idx+=NT){
        int m=idx/112, i=idx-m*112;
        float v=(i<H_)?fmaxf(fmaf(uS[m],W1[i],fmaf(uS[128+m],W1[H_+i],b1[i])),0.f):0.f;
        hS[m*SAH+i]=__float2bfloat16(v);
    }
    CPA_WAIT0(); __syncthreads();

    // ---- GEMM2: 7 n-tiles, hi+lo bf16, k = 7x16 in two halves ----
    {
        __nv_bfloat16* Bh=Bb; __nv_bfloat16* Bl=Bb+64*SB2;
        FragA fa; FragB fb; FragC fc[7];
        #pragma unroll
        for(int t=0;t<7;++t) wmma::fill_fragment(fc[t],0.f);
        for(int k=0;k<4;++k){
            wmma::load_matrix_sync(fa, hS+(w*16)*SAH+k*16, SAH);
            #pragma unroll
            for(int t=0;t<7;++t){
                wmma::load_matrix_sync(fb, Bh+k*16*SB2+t*16, SB2); wmma::mma_sync(fc[t],fa,fb,fc[t]);
                wmma::load_matrix_sync(fb, Bl+k*16*SB2+t*16, SB2); wmma::mma_sync(fc[t],fa,fb,fc[t]);
            }
        }
        __syncthreads();
        stage_w2(Bb, 64, 36, tid);          // half1: rows 64..99 -> buf rows 0..35
        // zero buf rows 36..47 (both parts)
        for(int i=tid;i<2*672;i+=NT){
            int part=i>=672, j=part? i-672:i;
            ((uint32_t*)(Bb+part*(64*SB2)))[2016+j]=0u;
        }
        CPA_COMMIT(); CPA_WAIT0(); __syncthreads();
        for(int k=4;k<7;++k){
            wmma::load_matrix_sync(fa, hS+(w*16)*SAH+k*16, SAH);
            #pragma unroll
            for(int t=0;t<7;++t){
                wmma::load_matrix_sync(fb, Bh+(k-4)*16*SB2+t*16, SB2); wmma::mma_sync(fc[t],fa,fb,fc[t]);
                wmma::load_matrix_sync(fb, Bl+(k-4)*16*SB2+t*16, SB2); wmma::mma_sync(fc[t],fa,fb,fc[t]);
            }
        }
        // h2 writeback (warp-private rows); cols 100..111 auto-zero (pad weights+bias)
        #pragma unroll
        for(int t=0;t<7;++t){
            wmma::store_matrix_sync(sc, fc[t], 16, wmma::mem_row_major);
            __syncwarp();
            for(int e2=lid;e2<256;e2+=32){
                int r=e2>>4, c2=e2&15, j=t*16+c2;
                hS[(w*16+r)*SAH+j]=__float2bfloat16(fmaxf(sc[e2]+b2S[j],0.f));
            }
            __syncwarp();
        }
    }
    __syncthreads();

    // ---- GEMM3: 8 chunks of (32 LP + 32 MU); A-fragments hoisted into registers ----
    for(int i=tid;i<2*432;i+=NT){
        int part=i>=432, j=part? i-432:i;
        ((uint32_t*)(Bb+part*(112*SB3E)))[3600+j]=0u;   // zero B rows 100..111
    }
    stage3(Bb, 0, tid); CPA_COMMIT(); CPA_WAIT0(); __syncthreads();

    FragA faA[7];
    #pragma unroll
    for(int k=0;k<7;++k)
        wmma::load_matrix_sync(faA[k], hS+(w*16)*SAH+k*16, SAH);

    __nv_bfloat16* B3h=Bb; __nv_bfloat16* B3l=Bb+112*SB3E;
    for(int c=0;c<8;++c){
        FragB fb; FragC fL[2], fM[2];
        #pragma unroll
        for(int t=0;t<2;++t){ wmma::fill_fragment(fL[t],0.f); wmma::fill_fragment(fM[t],0.f); }
        #pragma unroll
        for(int k=0;k<7;++k){
            #pragma unroll
            for(int t=0;t<2;++t){
                wmma::load_matrix_sync(fb, B3h+k*16*SB3E+t*16, SB3E);    wmma::mma_sync(fL[t],faA[k],fb,fL[t]);
                wmma::load_matrix_sync(fb, B3l+k*16*SB3E+t*16, SB3E);    wmma::mma_sync(fL[t],faA[k],fb,fL[t]);
                wmma::load_matrix_sync(fb, B3h+k*16*SB3E+32+t*16, SB3E); wmma::mma_sync(fM[t],faA[k],fb,fM[t]);
                wmma::load_matrix_sync(fb, B3l+k*16*SB3E+32+t*16, SB3E); wmma::mma_sync(fM[t],faA[k],fb,fM[t]);
            }
        }
        __syncthreads();                       // buffer reads done
        if(c<7){ stage3(Bb, c+1, tid); CPA_COMMIT(); }
        // epilogue: exp + 5 reductions over 16 rows, per-warp partials
        #pragma unroll
        for(int t=0;t<2;++t){
            wmma::store_matrix_sync(sc,     fL[t], 16, wmma::mem_row_major);
            wmma::store_matrix_sync(sc+256, fM[t], 16, wmma::mem_row_major);
            __syncwarp();
            int col=lid&15, rh=lid>>4;
            int kg=c*32+t*16+col;
            float bl=b3S[kg], bm=b3S[256+kg];
            float a=0,b=0,cc=0,d=0,e=0;
            #pragma unroll
            for(int r8=0;r8<8;++r8){
                int r=rh*8+r8, gr=w*16+r;
                float u0=uS[gr], u1=uS[128+gr];
                float p =__expf(sc[r*16+col]+bl);
                float pm=p*(sc[256+r*16+col]+bm);
                a+=p*u0*u0; b+=p*u0*u1; cc+=p*u1*u1; d+=pm*u0; e+=pm*u1;
            }
            a+=__shfl_xor_sync(0xffffffffu,a,16);
            b+=__shfl_xor_sync(0xffffffffu,b,16);
            cc+=__shfl_xor_sync(0xffffffffu,cc,16);
            d+=__shfl_xor_sync(0xffffffffu,d,16);
            e+=__shfl_xor_sync(0xffffffffu,e,16);
            if(lid<16){
                size_t base=(((size_t)s*5)*NBW+(size_t)(blk*8+w))*K_ + kg;
                const size_t cs=(size_t)NBW*K_;
                g_part[base]=a; g_part[base+cs]=b; g_part[base+2*cs]=cc;
                g_part[base+3*cs]=d; g_part[base+4*cs]=e;
            }
            __syncwarp();
        }
        if(c<7){ CPA_WAIT0(); __syncthreads(); }
    }
}

__global__ void __launch_bounds__(1024) stageB_kernel(const float* __restrict__ eps,
                                                      float* __restrict__ kl_out)
{
    __shared__ float sm5[5][4][K_];
    __shared__ float red[K_];
    const int s=blockIdx.x, tid=threadIdx.x, k=tid&255, q=tid>>8;
    const float* base=g_part+((size_t)s*5*NBW)*K_+k;
    const size_t cs=(size_t)NBW*K_;
    float A=0,B=0,C=0,dd=0,ee=0;
    for(int b=q*512;b<q*512+512;++b){
        size_t o=(size_t)b*K_;
        A+=base[o]; B+=base[cs+o]; C+=base[2*cs+o]; dd+=base[3*cs+o]; ee+=base[4*cs+o];
    }
    sm5[0][q][k]=A; sm5[1][q][k]=B; sm5[2][q][k]=C; sm5[3][q][k]=dd; sm5[4][q][k]=ee;
    __syncthreads();
    if(q==0){
        A =sm5[0][0][k]+sm5[0][1][k]+sm5[0][2][k]+sm5[0][3][k]+1.f;
        B =sm5[1][0][k]+sm5[1][1][k]+sm5[1][2][k]+sm5[1][3][k];
        C =sm5[2][0][k]+sm5[2][1][k]+sm5[2][2][k]+sm5[2][3][k]+1.f;
        dd=sm5[3][0][k]+sm5[3][1][k]+sm5[3][2][k]+sm5[3][3][k];
        ee=sm5[4][0][k]+sm5[4][1][k]+sm5[4][2][k]+sm5[4][3][k];
        float det=A*C-B*B, inv=1.f/det;
        float c00=C*inv, c01=-B*inv, c11=A*inv;
        float qm0=c00*dd+c01*ee, qm1=c01*dd+c11*ee;
        float l00=sqrtf(c00), l10=c01/l00, l11=sqrtf(fmaxf(c11-l10*l10,0.f));
        float e0=eps[(s*K_+k)*2], e1=eps[(s*K_+k)*2+1];
        g_w[(s*K_+k)*2]  =qm0+l00*e0;
        g_w[(s*K_+k)*2+1]=qm1+l10*e0+l11*e1;
        red[k]=0.5f*((c00+c11)+(qm0*qm0+qm1*qm1)-2.f+logf(det));
    }
    __syncthreads();
    for(int off=128;off;off>>=1){
        if(tid<off) red[tid]+=red[tid+off];
        __syncthreads();
    }
    if(tid==0) kl_out[s]=red[0];
}

__global__ void __launch_bounds__(256)
stageC_kernel(const float* __restrict__ U, float* __restrict__ out)
{
    __shared__ float w0s[K_],w1s[K_],u0s[64],u1s[64];
    const int s=blockIdx.y, n0=blockIdx.x*64, tid=threadIdx.x;
    w0s[tid]=g_w[(s*K_+tid)*2];
    w1s[tid]=g_w[(s*K_+tid)*2+1];
    if(tid<64){
        const float* up=U+((size_t)(s*N_+n0+tid)<<1);
        u0s[tid]=up[0]; u1s[tid]=up[1];
    }
    __syncthreads();
    const int kq=tid&63, r=tid>>6;
    #pragma unroll
    for(int nn=0;nn<16;++nn){
        int nl=nn*4+r;
        float u0=u0s[nl],u1=u1s[nl];
        int k=kq*4;
        float4 o;
        o.x=fmaxf(fmaf(u0,w0s[k],u1*w1s[k]),0.f);
        o.y=fmaxf(fmaf(u0,w0s[k+1],u1*w1s[k+1]),0.f);
        o.z=fmaxf(fmaf(u0,w0s[k+2],u1*w1s[k+2]),0.f);
        o.w=fmaxf(fmaf(u0,w0s[k+3],u1*w1s[k+3]),0.f);
        reinterpret_cast<float4*>(out)[(((size_t)(s*N_+n0+nl))*K_+k)>>2]=o;
    }
}

extern "C" void kernel_launch(void* const* d_in, const int* in_sizes, int n_in,
                              void* d_out, int out_size)
{
    const float* U  =(const float*)d_in[0];
    const float* eps=(const float*)d_in[1];
    const float* W1 =(const float*)d_in[2];
    const float* b1 =(const float*)d_in[3];
    const float* W2 =(const float*)d_in[4];
    const float* b2 =(const float*)d_in[5];
    const float* W3 =(const float*)d_in[6];
    const float* b3 =(const float*)d_in[7];
    float* out=(float*)d_out;

    cudaFuncSetAttribute((const void*)stageA_kernel,
                         cudaFuncAttributeMaxDynamicSharedMemorySize, SMEM_TOTAL);
    round_kernel<<<(H_*512+255)/256,256>>>(W2,W3);
    stageA_kernel<<<dim3(NB,S_),NT,SMEM_TOTAL>>>(U,W1,b1,b2,b3);
    stageB_kernel<<<S_,1024>>>(eps, out+(out_size-S_));
    stageC_kernel<<<dim3(N_/64,S_),256>>>(U,out);
}

// round 17
// speedup vs baseline: 2.1647x; 1.0276x over previous
#include <cuda_runtime.h>
#include <cuda_bf16.h>
#include <mma.h>
#include <cstdint>
using namespace nvcuda;

#define S_ 4
#define N_ 32768
#define K_ 256
#define H_ 100
#define NB 256
#define NBW 2048
#define NT 256
#define SAH 112          // hS stride (bf16 elements)
#define SB2 112          // GEMM2 B stride (elements)
#define SB3E 72          // GEMM3 B stride (elements)
#define SCW 1344         // per-warp scratch floats

#define OFF_HS 0
#define OFF_B  28672
#define OFF_SC 60928
#define OFF_US (OFF_SC+8*SCW*4)
#define OFF_B2 (OFF_US+1024)
#define OFF_B3 (OFF_B2+448)
#define SMEM_TOTAL (OFF_B3+2048)

__device__ __nv_bfloat16 g_w2h[H_*112], g_w2l[H_*112];   // padded cols 100..111 = 0
__device__ __nv_bfloat16 g_w3h[H_*512], g_w3l[H_*512];
__device__ float g_part[(size_t)S_*5*NBW*K_];
__device__ float g_w[S_*K_*2];

static __device__ __forceinline__ unsigned smem_u32(const void* p){
    return (unsigned)__cvta_generic_to_shared(p);
}
static __device__ __forceinline__ void cpa16(unsigned dst, const void* src){
    asm volatile("cp.async.cg.shared.global [%0], [%1], 16;\n" :: "r"(dst), "l"(src));
}
#define CPA_COMMIT() asm volatile("cp.async.commit_group;\n" ::: "memory")
#define CPA_WAIT0()  asm volatile("cp.async.wait_group 0;\n" ::: "memory")

typedef wmma::fragment<wmma::matrix_a,16,16,16,__nv_bfloat16,wmma::row_major> FragA;
typedef wmma::fragment<wmma::matrix_b,16,16,16,__nv_bfloat16,wmma::row_major> FragB;
typedef wmma::fragment<wmma::accumulator,16,16,16,float> FragC;

__global__ void round_kernel(const float* __restrict__ W2, const float* __restrict__ W3){
    int i = blockIdx.x*256 + threadIdx.x;
    if(i < H_*112){
        int r=i/112, c=i-r*112;
        float v = (c<H_)? W2[r*H_+c] : 0.f;
        __nv_bfloat16 h=__float2bfloat16(v);
        g_w2h[i]=h; g_w2l[i]=__float2bfloat16(v-__bfloat162float(h));
    }
    if(i < H_*512){
        float v=W3[i];
        __nv_bfloat16 h=__float2bfloat16(v);
        g_w3h[i]=h; g_w3l[i]=__float2bfloat16(v-__bfloat162float(h));
    }
}

// stage W3 chunk c: LP cols c*32.. -> cols 0..31, MU cols 256+c*32.. -> cols 32..63 (hi & lo)
static __device__ __forceinline__ void stage3(__nv_bfloat16* Bb, int c, int tid){
    for(int idx=tid; idx<1600; idx+=NT){
        int part = idx>=800, j = part? idx-800 : idx;
        int r=j>>3, t=j&7, mu=t>>2, sg=t&3;
        const __nv_bfloat16* src = (part? g_w3l : g_w3h) + (size_t)r*512 + mu*256 + c*32 + sg*8;
        cpa16(smem_u32(Bb + part*(112*SB3E) + r*SB3E + mu*32 + sg*8), src);
    }
}
// stage W2 rows r0..r0+rn-1 into buffer rows 0..rn-1 (hi & lo, 14x8 cols = 112)
static __device__ __forceinline__ void stage_w2(__nv_bfloat16* Bb, int r0, int rn, int tid){
    for(int idx=tid; idx<2*rn*14; idx+=NT){
        int part = idx>=rn*14, j = part? idx-rn*14 : idx;
        int r=j/14, u=j-r*14;
        const __nv_bfloat16* src = (part? g_w2l : g_w2h) + (r0+r)*112 + u*8;
        cpa16(smem_u32(Bb + part*(64*SB2) + r*SB2 + u*8), src);
    }
}

__global__ void __launch_bounds__(NT,2)
stageA_kernel(const float* __restrict__ U,  const float* __restrict__ W1,
              const float* __restrict__ b1, const float* __restrict__ b2,
              const float* __restrict__ b3)
{
    extern __shared__ char smc[];
    __nv_bfloat16* hS =(__nv_bfloat16*)(smc+OFF_HS);
    __nv_bfloat16* Bb =(__nv_bfloat16*)(smc+OFF_B);
    float* SC =(float*)(smc+OFF_SC);
    float* uS =(float*)(smc+OFF_US);
    float* b2S=(float*)(smc+OFF_B2);
    float* b3S=(float*)(smc+OFF_B3);
    const int tid=threadIdx.x, w=tid>>5, lid=tid&31;
    const int s=blockIdx.y, blk=blockIdx.x;
    float* sc = SC + w*SCW;

    if(tid<128){
        const float* up=U+((size_t)(s*N_+blk*128+tid)<<1);
        uS[tid]=up[0]; uS[128+tid]=up[1];
    }
    if(tid<112) b2S[tid]=(tid<H_)?b2[tid]:0.f;
    for(int i=tid;i<512;i+=NT) b3S[i]=b3[i];

    stage_w2(Bb, 0, 64, tid);     // half0: rows 0..63  [group 1]
    CPA_COMMIT();
    __syncthreads();

    // h1 = relu(U@W1+b1) -> bf16; cols 100..111 zero
    for(int idx=tid;idx<128*112;idx+=NT){
        int m=idx/112, i=idx-m*112;
        float v=(i<H_)?fmaxf(fmaf(uS[m],W1[i],fmaf(uS[128+m],W1[H_+i],b1[i])),0.f):0.f;
        hS[m*SAH+i]=__float2bfloat16(v);
    }
    CPA_WAIT0(); __syncthreads();

    // ---- GEMM2: 7 n-tiles, hi+lo bf16, k = 7x16 in two halves ----
    {
        __nv_bfloat16* Bh=Bb; __nv_bfloat16* Bl=Bb+64*SB2;
        FragA fa; FragB fb; FragC fc[7];
        #pragma unroll
        for(int t=0;t<7;++t) wmma::fill_fragment(fc[t],0.f);
        for(int k=0;k<4;++k){
            wmma::load_matrix_sync(fa, hS+(w*16)*SAH+k*16, SAH);
            #pragma unroll
            for(int t=0;t<7;++t){
                wmma::load_matrix_sync(fb, Bh+k*16*SB2+t*16, SB2); wmma::mma_sync(fc[t],fa,fb,fc[t]);
                wmma::load_matrix_sync(fb, Bl+k*16*SB2+t*16, SB2); wmma::mma_sync(fc[t],fa,fb,fc[t]);
            }
        }
        __syncthreads();
        stage_w2(Bb, 64, 36, tid);          // half1: rows 64..99 -> buf rows 0..35
        for(int i=tid;i<2*672;i+=NT){
            int part=i>=672, j=part? i-672:i;
            ((uint32_t*)(Bb+part*(64*SB2)))[2016+j]=0u;   // zero buf rows 36..47
        }
        CPA_COMMIT(); CPA_WAIT0(); __syncthreads();
        for(int k=4;k<7;++k){
            wmma::load_matrix_sync(fa, hS+(w*16)*SAH+k*16, SAH);
            #pragma unroll
            for(int t=0;t<7;++t){
                wmma::load_matrix_sync(fb, Bh+(k-4)*16*SB2+t*16, SB2); wmma::mma_sync(fc[t],fa,fb,fc[t]);
                wmma::load_matrix_sync(fb, Bl+(k-4)*16*SB2+t*16, SB2); wmma::mma_sync(fc[t],fa,fb,fc[t]);
            }
        }
        // h2 writeback (warp-private rows); cols 100..111 auto-zero (pad weights+bias)
        #pragma unroll
        for(int t=0;t<7;++t){
            wmma::store_matrix_sync(sc, fc[t], 16, wmma::mem_row_major);
            __syncwarp();
            for(int e2=lid;e2<256;e2+=32){
                int r=e2>>4, c2=e2&15, j=t*16+c2;
                hS[(w*16+r)*SAH+j]=__float2bfloat16(fmaxf(sc[e2]+b2S[j],0.f));
            }
            __syncwarp();
        }
    }
    __syncthreads();

    // ---- GEMM3: 8 chunks of (32 LP + 32 MU); A hoisted; lane-per-column epilogue ----
    for(int i=tid;i<2*432;i+=NT){
        int part=i>=432, j=part? i-432:i;
        ((uint32_t*)(Bb+part*(112*SB3E)))[3600+j]=0u;   // zero B rows 100..111
    }
    stage3(Bb, 0, tid); CPA_COMMIT(); CPA_WAIT0(); __syncthreads();

    FragA faA[7];
    #pragma unroll
    for(int k=0;k<7;++k)
        wmma::load_matrix_sync(faA[k], hS+(w*16)*SAH+k*16, SAH);

    __nv_bfloat16* B3h=Bb; __nv_bfloat16* B3l=Bb+112*SB3E;
    for(int c=0;c<8;++c){
        FragB fb; FragC fL[2], fM[2];
        #pragma unroll
        for(int t=0;t<2;++t){ wmma::fill_fragment(fL[t],0.f); wmma::fill_fragment(fM[t],0.f); }
        #pragma unroll
        for(int k=0;k<7;++k){
            #pragma unroll
            for(int t=0;t<2;++t){
                wmma::load_matrix_sync(fb, B3h+k*16*SB3E+t*16, SB3E);    wmma::mma_sync(fL[t],faA[k],fb,fL[t]);
                wmma::load_matrix_sync(fb, B3l+k*16*SB3E+t*16, SB3E);    wmma::mma_sync(fL[t],faA[k],fb,fL[t]);
                wmma::load_matrix_sync(fb, B3h+k*16*SB3E+32+t*16, SB3E); wmma::mma_sync(fM[t],faA[k],fb,fM[t]);
                wmma::load_matrix_sync(fb, B3l+k*16*SB3E+32+t*16, SB3E); wmma::mma_sync(fM[t],faA[k],fb,fM[t]);
            }
        }
        __syncthreads();                       // buffer reads done
        if(c<7){ stage3(Bb, c+1, tid); CPA_COMMIT(); }

        // epilogue: 4 tiles at ldm=20; tile1 offset 336 (==16 mod 32) => conflict-free
        wmma::store_matrix_sync(sc,      fL[0], 20, wmma::mem_row_major);
        wmma::store_matrix_sync(sc+336,  fL[1], 20, wmma::mem_row_major);
        wmma::store_matrix_sync(sc+672,  fM[0], 20, wmma::mem_row_major);
        wmma::store_matrix_sync(sc+1008, fM[1], 20, wmma::mem_row_major);
        __syncwarp();
        {
            int kg = c*32 + lid;
            float bl=b3S[kg], bm=b3S[256+kg];
            const float* Lp = sc + (lid>>4)*336 + (lid&15);
            const float* Mp = Lp + 672;
            float a=0,b=0,cc=0,d=0,e=0;
            #pragma unroll
            for(int r=0;r<16;++r){
                int gr=w*16+r;
                float u0=uS[gr], u1=uS[128+gr];
                float p =__expf(Lp[r*20]+bl);
                float pm=p*(Mp[r*20]+bm);
                a+=p*u0*u0; b+=p*u0*u1; cc+=p*u1*u1; d+=pm*u0; e+=pm*u1;
            }
            size_t base=(((size_t)s*5)*NBW+(size_t)(blk*8+w))*K_ + kg;
            const size_t cs=(size_t)NBW*K_;
            g_part[base]=a; g_part[base+cs]=b; g_part[base+2*cs]=cc;
            g_part[base+3*cs]=d; g_part[base+4*cs]=e;
        }
        __syncwarp();
        if(c<7){ CPA_WAIT0(); __syncthreads(); }
    }
}

__global__ void __launch_bounds__(1024) stageB_kernel(const float* __restrict__ eps,
                                                      float* __restrict__ kl_out)
{
    __shared__ float sm5[5][4][K_];
    __shared__ float red[K_];
    const int s=blockIdx.x, tid=threadIdx.x, k=tid&255, q=tid>>8;
    const float* base=g_part+((size_t)s*5*NBW)*K_+k;
    const size_t cs=(size_t)NBW*K_;
    float A=0,B=0,C=0,dd=0,ee=0;
    for(int b=q*512;b<q*512+512;++b){
        size_t o=(size_t)b*K_;
        A+=base[o]; B+=base[cs+o]; C+=base[2*cs+o]; dd+=base[3*cs+o]; ee+=base[4*cs+o];
    }
    sm5[0][q][k]=A; sm5[1][q][k]=B; sm5[2][q][k]=C; sm5[3][q][k]=dd; sm5[4][q][k]=ee;
    __syncthreads();
    if(q==0){
        A =sm5[0][0][k]+sm5[0][1][k]+sm5[0][2][k]+sm5[0][3][k]+1.f;
        B =sm5[1][0][k]+sm5[1][1][k]+sm5[1][2][k]+sm5[1][3][k];
        C =sm5[2][0][k]+sm5[2][1][k]+sm5[2][2][k]+sm5[2][3][k]+1.f;
        dd=sm5[3][0][k]+sm5[3][1][k]+sm5[3][2][k]+sm5[3][3][k];
        ee=sm5[4][0][k]+sm5[4][1][k]+sm5[4][2][k]+sm5[4][3][k];
        float det=A*C-B*B, inv=1.f/det;
        float c00=C*inv, c01=-B*inv, c11=A*inv;
        float qm0=c00*dd+c01*ee, qm1=c01*dd+c11*ee;
        float l00=sqrtf(c00), l10=c01/l00, l11=sqrtf(fmaxf(c11-l10*l10,0.f));
        float e0=eps[(s*K_+k)*2], e1=eps[(s*K_+k)*2+1];
        g_w[(s*K_+k)*2]  =qm0+l00*e0;
        g_w[(s*K_+k)*2+1]=qm1+l10*e0+l11*e1;
        red[k]=0.5f*((c00+c11)+(qm0*qm0+qm1*qm1)-2.f+logf(det));
    }
    __syncthreads();
    for(int off=128;off;off>>=1){
        if(tid<off) red[tid]+=red[tid+off];
        __syncthreads();
    }
    if(tid==0) kl_out[s]=red[0];
}

__global__ void __launch_bounds__(256)
stageC_kernel(const float* __restrict__ U, float* __restrict__ out)
{
    __shared__ float w0s[K_],w1s[K_],u0s[64],u1s[64];
    const int s=blockIdx.y, n0=blockIdx.x*64, tid=threadIdx.x;
    w0s[tid]=g_w[(s*K_+tid)*2];
    w1s[tid]=g_w[(s*K_+tid)*2+1];
    if(tid<64){
        const float* up=U+((size_t)(s*N_+n0+tid)<<1);
        u0s[tid]=up[0]; u1s[tid]=up[1];
    }
    __syncthreads();
    const int kq=tid&63, r=tid>>6;
    #pragma unroll
    for(int nn=0;nn<16;++nn){
        int nl=nn*4+r;
        float u0=u0s[nl],u1=u1s[nl];
        int k=kq*4;
        float4 o;
        o.x=fmaxf(fmaf(u0,w0s[k],u1*w1s[k]),0.f);
        o.y=fmaxf(fmaf(u0,w0s[k+1],u1*w1s[k+1]),0.f);
        o.z=fmaxf(fmaf(u0,w0s[k+2],u1*w1s[k+2]),0.f);
        o.w=fmaxf(fmaf(u0,w0s[k+3],u1*w1s[k+3]),0.f);
        reinterpret_cast<float4*>(out)[(((size_t)(s*N_+n0+nl))*K_+k)>>2]=o;
    }
}

extern "C" void kernel_launch(void* const* d_in, const int* in_sizes, int n_in,
                              void* d_out, int out_size)
{
    const float* U  =(const float*)d_in[0];
    const float* eps=(const float*)d_in[1];
    const float* W1 =(const float*)d_in[2];
    const float* b1 =(const float*)d_in[3];
    const float* W2 =(const float*)d_in[4];
    const float* b2 =(const float*)d_in[5];
    const float* W3 =(const float*)d_in[6];
    const float* b3 =(const float*)d_in[7];
    float* out=(float*)d_out;

    cudaFuncSetAttribute((const void*)stageA_kernel,
                         cudaFuncAttributeMaxDynamicSharedMemorySize, SMEM_TOTAL);
    round_kernel<<<(H_*512+255)/256,256>>>(W2,W3);
    stageA_kernel<<<dim3(NB,S_),NT,SMEM_TOTAL>>>(U,W1,b1,b2,b3);
    stageB_kernel<<<S_,1024>>>(eps, out+(out_size-S_));
    stageC_kernel<<<dim3(N_/64,S_),256>>>(U,out);
}